// round 8
// baseline (speedup 1.0000x reference)
#include <cuda_runtime.h>

// Problem constants (fixed shapes for this problem instance)
#define NBOX   2048
#define NBATCH 16
#define AH     256
#define AW     256
#define GRID   1024  // NBATCH * 64 row-groups (4 rows per block)

__device__ float        g_partial[GRID];
__device__ unsigned int g_count = 0;

// bce = max(l,0) - l*m + log1p(exp(-|l|)); softplus arg in (1,2] -> safe fast math
__device__ __forceinline__ float bce_elem(float l, unsigned mb) {
    float t  = __expf(-fabsf(l));
    float sp = __logf(1.0f + t);
    float z  = fmaxf(l, 0.0f) - (mb ? l : 0.0f);
    return z + sp;
}

__global__ __launch_bounds__(256, 8)
void la_loss_kernel(const float* __restrict__ am,
                    const float* __restrict__ tgt,
                    float* __restrict__ out)
{
    const int tid   = threadIdx.x;
    const int blk   = blockIdx.x;
    const int batch = blk >> 6;   // 0..15
    const int rg    = blk & 63;   // row group: rows [rg*4, rg*4+4)

    // ---- Prefetch this block's 1024 logits (4 rows x 256) now; used in Phase 2b.
    const float4* am4  = (const float4*)am;
    const float4  v    = am4[(size_t)blk * 256 + tid];

    __shared__ ushort4  s_rect[NBOX];        // compacted non-empty rects (16 KB worst)
    __shared__ unsigned s_rowmask[4 * 8];    // 4 rows x 256 bits
    __shared__ float    s_warp[8];
    __shared__ int      s_has;               // any box with bidx==batch (has_box)
    __shared__ int      s_nrect;             // compacted rect count
    __shared__ unsigned s_last;

    if (tid == 0) { s_has = 0; s_nrect = 0; }
    if (tid < 32) s_rowmask[tid] = 0u;
    __syncthreads();

    // ---- Phase 1: scan + warp-aggregated compaction of this batch's boxes ----
    // Order of compacted rects is irrelevant: the mask is a pure OR-union.
    {
        const float fb   = (float)batch;
        const int   lane = tid & 31;
        #pragma unroll
        for (int k = 0; k < NBOX / 256; k++) {
            const int    i = tid + (k << 8);
            const float* t = tgt + (size_t)i * 6;
            const bool match = (t[0] == fb);

            unsigned mmask = __ballot_sync(0xFFFFFFFFu, match);
            if (mmask && lane == 0) atomicOr((unsigned*)&s_has, 1u);

            bool    store = false;
            ushort4 rect;
            if (match) {
                float xc = t[2], yc = t[3], bw = t[4], bh = t[5];
                float x1 = 1024.0f * (xc - bw * 0.5f);
                float y1 = 1024.0f * (yc - bh * 0.5f);
                float x2 = 1024.0f * (xc + bw * 0.5f);
                float y2 = 1024.0f * (yc + bh * 0.5f);
                bool valid = (x1 <= 1024.0f) && (y1 <= 1024.0f) &&
                             (x2 <= 1024.0f) && (y2 <= 1024.0f);
                int X1 = max(0, (int)truncf(x1 * 0.25f));
                int Y1 = max(0, (int)truncf(y1 * 0.25f));
                int X2 = max(0, min(AW, (int)(ceilf(x2 * 0.25f) + 1.0f)));
                int Y2 = max(0, min(AH, (int)(ceilf(y2 * 0.25f) + 1.0f)));
                store = valid && (X2 > X1) && (Y2 > Y1);
                rect  = make_ushort4((unsigned short)X1, (unsigned short)X2,
                                     (unsigned short)Y1, (unsigned short)Y2);
            }
            unsigned smask = __ballot_sync(0xFFFFFFFFu, store);
            int base = 0;
            if (lane == 0 && smask) base = atomicAdd(&s_nrect, __popc(smask));
            base = __shfl_sync(0xFFFFFFFFu, base, 0);
            if (store) {
                int pos = base + __popc(smask & ((1u << lane) - 1u));
                s_rect[pos] = rect;
            }
        }
    }
    __syncthreads();
    const int nrect = s_nrect;

    // ---- Phase 2a: rasterize union bitmask for this block's 4 rows ----
    // ty = tid>>6 selects row (4 rows), lane64 = tid&63 strides over rects
    {
        const int ty     = tid >> 6;
        const int lane64 = tid & 63;
        const int y      = (rg << 2) + ty;
        for (int i = lane64; i < nrect; i += 64) {
            ushort4 r = s_rect[i];
            if (y >= (int)r.z && y < (int)r.w) {
                int X1 = (int)r.x, X2 = (int)r.y;
                int w0 = X1 >> 5;
                int w1 = (X2 - 1) >> 5;
                for (int w = w0; w <= w1; w++) {
                    int lo = X1 - (w << 5); lo = (lo < 0) ? 0 : lo;   // 0..31
                    int hi = X2 - (w << 5);                            // >=1
                    unsigned mh  = (hi >= 32) ? 0xFFFFFFFFu : ((1u << hi) - 1u);
                    unsigned msk = mh & ~((1u << lo) - 1u);
                    atomicOr(&s_rowmask[(ty << 3) + w], msk);
                }
            }
        }
    }
    __syncthreads();

    // ---- Phase 2b: BCE over prefetched logits (4 elems/thread) ----
    float sum;
    {
        int ty  = tid >> 6;                  // 64 float4 per row
        int col = (tid & 63) << 2;           // starting bit (mult of 4)
        unsigned bits = s_rowmask[(ty << 3) + (col >> 5)] >> (col & 31);
        sum  = bce_elem(v.x,  bits       & 1u);
        sum += bce_elem(v.y, (bits >> 1) & 1u);
        sum += bce_elem(v.z, (bits >> 2) & 1u);
        sum += bce_elem(v.w, (bits >> 3) & 1u);
    }

    // ---- Phase 3: block reduce (fixed order), publish partial ----
    {
        #pragma unroll
        for (int off = 16; off; off >>= 1)
            sum += __shfl_down_sync(0xFFFFFFFFu, sum, off);
        if ((tid & 31) == 0) s_warp[tid >> 5] = sum;
    }
    __syncthreads();
    if (tid == 0) {
        float tot = 0.0f;
        #pragma unroll
        for (int w = 0; w < 8; w++) tot += s_warp[w];   // fixed order
        float partial = s_has ? tot * (1.0f / 65536.0f) : 0.0f;
        g_partial[blk] = partial;
        __threadfence();
        unsigned prev = atomicAdd(&g_count, 1u);
        s_last = (prev == (unsigned)(gridDim.x - 1)) ? 1u : 0u;
    }
    __syncthreads();

    // ---- Phase 4: last block sums all partials, fixed order (deterministic) ----
    if (s_last) {
        __threadfence();
        volatile float* gp = g_partial;
        float t0 = (gp[tid]       + gp[tid + 256]) +
                   (gp[tid + 512] + gp[tid + 768]);
        #pragma unroll
        for (int off = 16; off; off >>= 1)
            t0 += __shfl_down_sync(0xFFFFFFFFu, t0, off);
        if ((tid & 31) == 0) s_warp[tid >> 5] = t0;
        __syncthreads();
        if (tid == 0) {
            float tot = 0.0f;
            #pragma unroll
            for (int w = 0; w < 8; w++) tot += s_warp[w];  // fixed order
            out[0]  = tot;
            g_count = 0u;   // reset for next graph replay
        }
    }
}

extern "C" void kernel_launch(void* const* d_in, const int* in_sizes, int n_in,
                              void* d_out, int out_size)
{
    const float* am  = (const float*)d_in[0];  // attention_mask (16,1,256,256) f32
    const float* tgt = (const float*)d_in[1];  // target (2048,6) f32
    (void)in_sizes; (void)n_in; (void)out_size;
    la_loss_kernel<<<GRID, 256>>>(am, tgt, (float*)d_out);
}